// round 2
// baseline (speedup 1.0000x reference)
#include <cuda_runtime.h>
#include <cstddef>

#define VOCAB 32000
#define EMB   32
#define REC   16
#define SEQ   256
#define BATCH 32

// Scratch (allocation-free rule: __device__ globals)
__device__ float g_hidden[SEQ * BATCH * REC];   // hidden[s][b][r]
__device__ float g_iproj [SEQ * BATCH * REC];   // x_t@U^T + b1 + b2

// Packed f32x2 FMA (Blackwell; ptxas won't auto-fuse — PTX only)
__device__ __forceinline__ float2 ffma2(float2 a, float2 b, float2 c) {
    union { float2 f; unsigned long long u; } A, B, C, D;
    A.f = a; B.f = b; C.f = c;
    asm("fma.rn.f32x2 %0, %1, %2, %3;" : "=l"(D.u) : "l"(A.u), "l"(B.u), "l"(C.u));
    return D.f;
}

// ---------------------------------------------------------------------------
// Kernel 1: input projection. iproj[s,b,r] = emb[tok[s,b]] . U[r] + b1[r]+b2[r]
// ---------------------------------------------------------------------------
__global__ void iproj_kernel(const int* __restrict__ tok,
                             const float* __restrict__ emb,
                             const float* __restrict__ U,
                             const float* __restrict__ b1,
                             const float* __restrict__ b2) {
    int idx = blockIdx.x * blockDim.x + threadIdx.x;   // s*512 + b*16 + r
    if (idx >= SEQ * BATCH * REC) return;
    int r  = idx & (REC - 1);
    int sb = idx >> 4;
    int t  = tok[sb];
    const float4* e = (const float4*)(emb + (size_t)t * EMB);
    const float4* u = (const float4*)(U + (size_t)r * EMB);
    float acc = b1[r] + b2[r];
#pragma unroll
    for (int q = 0; q < EMB / 4; q++) {
        float4 ev = e[q], uv = u[q];
        acc = fmaf(ev.x, uv.x, acc);
        acc = fmaf(ev.y, uv.y, acc);
        acc = fmaf(ev.z, uv.z, acc);
        acc = fmaf(ev.w, uv.w, acc);
    }
    g_iproj[idx] = acc;
}

// ---------------------------------------------------------------------------
// Kernel 2: sequential recurrence (single CTA).
// hidden[t] = h_t  (pre-update, h_0 = h0 broadcast);  h_{t+1} = tanh(iproj_t + W h_t)
// 256 threads: thread (bp, r) owns batches b0=2*bp, b1=2*bp+1 for row r.
// ---------------------------------------------------------------------------
__global__ void __launch_bounds__(256) rnn_kernel(const float* __restrict__ W,
                                                  const float* __restrict__ h0) {
    __shared__ float2 hd[2][REC][17];   // hd[buf][j][bp] = {h[2bp][j], h[2bp+1][j]}
    int tid = threadIdx.x;
    int bp  = tid >> 4;        // 0..15
    int r   = tid & (REC - 1); // 0..15

    float2 wdup[REC];
#pragma unroll
    for (int j = 0; j < REC; j++) {
        float w = W[r * REC + j];
        wdup[j] = make_float2(w, w);
    }

    float c0 = h0[r], c1 = c0;
    hd[0][r][bp] = make_float2(c0, c1);
    __syncthreads();

    const int base = bp * 2 * REC + r;     // (b0)*16 + r ; +REC for b1

    // prefetch pipeline depth 2
    float ip0[2], ip1[2];
    ip0[0] = g_iproj[0 * 512 + base];  ip1[0] = g_iproj[0 * 512 + base + REC];
    ip0[1] = g_iproj[1 * 512 + base];  ip1[1] = g_iproj[1 * 512 + base + REC];

    for (int t = 0; t < SEQ; t++) {
        // store hidden[t] = current h (pre-update)
        g_hidden[t * 512 + base]       = c0;
        g_hidden[t * 512 + base + REC] = c1;

        if (t < SEQ - 1) {
            int rb = t & 1, wb = rb ^ 1;
            float2 acc = make_float2(ip0[rb], ip1[rb]);
            // prefetch t+2 into the slot we just consumed
            if (t + 2 < SEQ) {
                ip0[rb] = g_iproj[(t + 2) * 512 + base];
                ip1[rb] = g_iproj[(t + 2) * 512 + base + REC];
            }
#pragma unroll
            for (int j = 0; j < REC; j++)
                acc = ffma2(hd[rb][j][bp], wdup[j], acc);
            // tanh(x) = 1 - 2/(e^{2x}+1)
            float e0 = __expf(2.0f * acc.x);
            float e1 = __expf(2.0f * acc.y);
            c0 = 1.0f - __fdividef(2.0f, e0 + 1.0f);
            c1 = 1.0f - __fdividef(2.0f, e1 + 1.0f);
            hd[wb][r][bp] = make_float2(c0, c1);
        }
        __syncthreads();
    }
}

// ---------------------------------------------------------------------------
// Kernel 3: logits + log_softmax, two recompute passes.
// One CTA per s. 320 threads; each thread owns 4 consecutive vocab rows per
// chunk (25 chunks of 1280). V rows live in registers pre-packed as f32x2
// pairs over v; h is duplicated {h,h} in shared and broadcast-read.
// ---------------------------------------------------------------------------
__global__ void __launch_bounds__(320, 1) logits_kernel(const float* __restrict__ V,
                                                        float* __restrict__ out) {
    const int s   = blockIdx.x;
    const int tid = threadIdx.x;

    __shared__ float2 hd[BATCH][REC];   // {h, h} duplicated for f32x2 broadcast
    __shared__ float  red[10][BATCH];
    __shared__ float  logZ[BATCH];

    for (int i = tid; i < BATCH * REC; i += 320) {
        float v = g_hidden[s * 512 + i];
        hd[i >> 4][i & (REC - 1)] = make_float2(v, v);
    }
    __syncthreads();

    float sumv[BATCH];
#pragma unroll
    for (int b = 0; b < BATCH; b++) sumv[b] = 0.0f;

    // ---------------- pass 1: sum of exp(logit) per (b) --------------------
    for (int c = 0; c < 25; c++) {
        int v0 = c * 1280 + tid * 4;
        float A[4][REC];
#pragma unroll
        for (int rr = 0; rr < 4; rr++) {
            const float4* q = (const float4*)(V + (size_t)(v0 + rr) * REC);
            float4 x0 = q[0], x1 = q[1], x2 = q[2], x3 = q[3];
            float* Ar = A[rr];
            ((float4*)Ar)[0] = x0; ((float4*)Ar)[1] = x1;
            ((float4*)Ar)[2] = x2; ((float4*)Ar)[3] = x3;
        }
        float2 p01[REC], p23[REC];
#pragma unroll
        for (int j = 0; j < REC; j++) {
            p01[j] = make_float2(A[0][j], A[1][j]);
            p23[j] = make_float2(A[2][j], A[3][j]);
        }
#pragma unroll
        for (int b = 0; b < BATCH; b++) {
            float2 a01 = make_float2(0.f, 0.f), a23 = make_float2(0.f, 0.f);
#pragma unroll
            for (int j = 0; j < REC; j++) {
                float2 h2 = hd[b][j];                 // broadcast LDS.64
                a01 = ffma2(h2, p01[j], a01);
                a23 = ffma2(h2, p23[j], a23);
            }
            sumv[b] += (__expf(a01.x) + __expf(a01.y)) +
                       (__expf(a23.x) + __expf(a23.y));
        }
    }

    // ---------------- reduce sumv across CTA -> logZ[b] --------------------
#pragma unroll
    for (int b = 0; b < BATCH; b++) {
        float v = sumv[b];
#pragma unroll
        for (int off = 16; off; off >>= 1)
            v += __shfl_xor_sync(0xffffffffu, v, off);
        sumv[b] = v;
    }
    int wid = tid >> 5, lane = tid & 31;
    if (lane == 0) {
#pragma unroll
        for (int b = 0; b < BATCH; b++) red[wid][b] = sumv[b];
    }
    __syncthreads();
    if (tid < BATCH) {
        float tot = 0.f;
#pragma unroll
        for (int w = 0; w < 10; w++) tot += red[w][tid];
        logZ[tid] = __logf(tot);
    }
    __syncthreads();

    // ---------------- pass 2: recompute logits, write log_softmax ----------
    for (int c = 0; c < 25; c++) {
        int v0 = c * 1280 + tid * 4;
        float A[4][REC];
#pragma unroll
        for (int rr = 0; rr < 4; rr++) {
            const float4* q = (const float4*)(V + (size_t)(v0 + rr) * REC);
            float4 x0 = q[0], x1 = q[1], x2 = q[2], x3 = q[3];
            float* Ar = A[rr];
            ((float4*)Ar)[0] = x0; ((float4*)Ar)[1] = x1;
            ((float4*)Ar)[2] = x2; ((float4*)Ar)[3] = x3;
        }
        float2 p01[REC], p23[REC];
#pragma unroll
        for (int j = 0; j < REC; j++) {
            p01[j] = make_float2(A[0][j], A[1][j]);
            p23[j] = make_float2(A[2][j], A[3][j]);
        }
#pragma unroll
        for (int b = 0; b < BATCH; b++) {
            float2 a01 = make_float2(0.f, 0.f), a23 = make_float2(0.f, 0.f);
#pragma unroll
            for (int j = 0; j < REC; j++) {
                float2 h2 = hd[b][j];
                a01 = ffma2(h2, p01[j], a01);
                a23 = ffma2(h2, p23[j], a23);
            }
            float z = logZ[b];
            float4 o = make_float4(a01.x - z, a01.y - z, a23.x - z, a23.y - z);
            *(float4*)(out + ((size_t)s * BATCH + b) * VOCAB + v0) = o;
        }
    }
}

// ---------------------------------------------------------------------------
extern "C" void kernel_launch(void* const* d_in, const int* in_sizes, int n_in,
                              void* d_out, int out_size) {
    const int*   tok = (const int*)  d_in[0];   // input_batch [SEQ, BATCH] int32
    const float* emb = (const float*)d_in[1];   // embedding   [VOCAB, EMB]
    const float* U   = (const float*)d_in[2];   // U [REC, EMB]
    const float* W   = (const float*)d_in[3];   // W [REC, REC]
    const float* V   = (const float*)d_in[4];   // V [VOCAB, REC]
    const float* b1  = (const float*)d_in[5];   // bias_1 [REC]
    const float* b2  = (const float*)d_in[6];   // bias_2 [REC]
    const float* h0  = (const float*)d_in[7];   // h0 [REC]
    float* out = (float*)d_out;                 // [SEQ, BATCH, VOCAB] f32

    iproj_kernel<<<(SEQ * BATCH * REC + 255) / 256, 256>>>(tok, emb, U, b1, b2);
    rnn_kernel<<<1, 256>>>(W, h0);
    logits_kernel<<<SEQ, 320>>>(V, out);
}

// round 3
// speedup vs baseline: 4.4206x; 4.4206x over previous
#include <cuda_runtime.h>
#include <cstddef>

#define VOCAB 32000
#define EMB   32
#define REC   16
#define SEQ   256
#define BATCH 32

// Scratch (allocation-free rule: __device__ globals)
__device__ float g_hidden[SEQ * BATCH * REC];   // hidden[s][b][r]
__device__ float g_iproj [SEQ * BATCH * REC];   // x_t@U^T + b1 + b2

// Packed f32x2 FMA (Blackwell; ptxas won't auto-fuse — PTX only)
__device__ __forceinline__ float2 ffma2(float2 a, float2 b, float2 c) {
    union { float2 f; unsigned long long u; } A, B, C, D;
    A.f = a; B.f = b; C.f = c;
    asm("fma.rn.f32x2 %0, %1, %2, %3;" : "=l"(D.u) : "l"(A.u), "l"(B.u), "l"(C.u));
    return D.f;
}

// ---------------------------------------------------------------------------
// Kernel 1: input projection. iproj[s,b,r] = emb[tok[s,b]] . U[r] + b1[r]+b2[r]
// ---------------------------------------------------------------------------
__global__ void iproj_kernel(const int* __restrict__ tok,
                             const float* __restrict__ emb,
                             const float* __restrict__ U,
                             const float* __restrict__ b1,
                             const float* __restrict__ b2) {
    int idx = blockIdx.x * blockDim.x + threadIdx.x;   // s*512 + b*16 + r
    if (idx >= SEQ * BATCH * REC) return;
    int r  = idx & (REC - 1);
    int sb = idx >> 4;
    int t  = tok[sb];
    const float4* e = (const float4*)(emb + (size_t)t * EMB);
    const float4* u = (const float4*)(U + (size_t)r * EMB);
    float acc = b1[r] + b2[r];
#pragma unroll
    for (int q = 0; q < EMB / 4; q++) {
        float4 ev = e[q], uv = u[q];
        acc = fmaf(ev.x, uv.x, acc);
        acc = fmaf(ev.y, uv.y, acc);
        acc = fmaf(ev.z, uv.z, acc);
        acc = fmaf(ev.w, uv.w, acc);
    }
    g_iproj[idx] = acc;
}

// ---------------------------------------------------------------------------
// Kernel 2: sequential recurrence (single CTA).
// hidden[t] = h_t (pre-update, h_0 = h0);  h_{t+1} = tanh(iproj_t + W h_t)
// ---------------------------------------------------------------------------
__global__ void __launch_bounds__(256) rnn_kernel(const float* __restrict__ W,
                                                  const float* __restrict__ h0) {
    __shared__ float2 hd[2][REC][17];   // hd[buf][j][bp] = {h[2bp][j], h[2bp+1][j]}
    int tid = threadIdx.x;
    int bp  = tid >> 4;        // 0..15
    int r   = tid & (REC - 1); // 0..15

    float2 wdup[REC];
#pragma unroll
    for (int j = 0; j < REC; j++) {
        float w = W[r * REC + j];
        wdup[j] = make_float2(w, w);
    }

    float c0 = h0[r], c1 = c0;
    hd[0][r][bp] = make_float2(c0, c1);
    __syncthreads();

    const int base = bp * 2 * REC + r;

    float ip0[2], ip1[2];
    ip0[0] = g_iproj[0 * 512 + base];  ip1[0] = g_iproj[0 * 512 + base + REC];
    ip0[1] = g_iproj[1 * 512 + base];  ip1[1] = g_iproj[1 * 512 + base + REC];

    for (int t = 0; t < SEQ; t++) {
        g_hidden[t * 512 + base]       = c0;
        g_hidden[t * 512 + base + REC] = c1;

        if (t < SEQ - 1) {
            int rb = t & 1, wb = rb ^ 1;
            float2 acc = make_float2(ip0[rb], ip1[rb]);
            if (t + 2 < SEQ) {
                ip0[rb] = g_iproj[(t + 2) * 512 + base];
                ip1[rb] = g_iproj[(t + 2) * 512 + base + REC];
            }
#pragma unroll
            for (int j = 0; j < REC; j++)
                acc = ffma2(hd[rb][j][bp], wdup[j], acc);
            float e0 = __expf(2.0f * acc.x);
            float e1 = __expf(2.0f * acc.y);
            c0 = 1.0f - __fdividef(2.0f, e0 + 1.0f);
            c1 = 1.0f - __fdividef(2.0f, e1 + 1.0f);
            hd[wb][r][bp] = make_float2(c0, c1);
        }
        __syncthreads();
    }
}

// ---------------------------------------------------------------------------
// V tile: 4 consecutive vocab rows packed as f32x2 over {row0,row1},{row2,row3}
// Named float4 temporaries + constant-index packing only — no pointer casts
// into local arrays, so everything promotes to registers.
// ---------------------------------------------------------------------------
struct VTile {
    float2 p01[REC];
    float2 p23[REC];
};

__device__ __forceinline__ VTile load_vtile(const float4* __restrict__ Vq, int v0) {
    // 4 rows x 16 floats = 16 contiguous float4 starting at row v0
    const float4* q = Vq + (size_t)v0 * 4;
    float4 r00 = q[0],  r01 = q[1],  r02 = q[2],  r03 = q[3];
    float4 r10 = q[4],  r11 = q[5],  r12 = q[6],  r13 = q[7];
    float4 r20 = q[8],  r21 = q[9],  r22 = q[10], r23 = q[11];
    float4 r30 = q[12], r31 = q[13], r32 = q[14], r33 = q[15];
    VTile t;
    t.p01[0]  = make_float2(r00.x, r10.x); t.p01[1]  = make_float2(r00.y, r10.y);
    t.p01[2]  = make_float2(r00.z, r10.z); t.p01[3]  = make_float2(r00.w, r10.w);
    t.p01[4]  = make_float2(r01.x, r11.x); t.p01[5]  = make_float2(r01.y, r11.y);
    t.p01[6]  = make_float2(r01.z, r11.z); t.p01[7]  = make_float2(r01.w, r11.w);
    t.p01[8]  = make_float2(r02.x, r12.x); t.p01[9]  = make_float2(r02.y, r12.y);
    t.p01[10] = make_float2(r02.z, r12.z); t.p01[11] = make_float2(r02.w, r12.w);
    t.p01[12] = make_float2(r03.x, r13.x); t.p01[13] = make_float2(r03.y, r13.y);
    t.p01[14] = make_float2(r03.z, r13.z); t.p01[15] = make_float2(r03.w, r13.w);
    t.p23[0]  = make_float2(r20.x, r30.x); t.p23[1]  = make_float2(r20.y, r30.y);
    t.p23[2]  = make_float2(r20.z, r30.z); t.p23[3]  = make_float2(r20.w, r30.w);
    t.p23[4]  = make_float2(r21.x, r31.x); t.p23[5]  = make_float2(r21.y, r31.y);
    t.p23[6]  = make_float2(r21.z, r31.z); t.p23[7]  = make_float2(r21.w, r31.w);
    t.p23[8]  = make_float2(r22.x, r32.x); t.p23[9]  = make_float2(r22.y, r32.y);
    t.p23[10] = make_float2(r22.z, r32.z); t.p23[11] = make_float2(r22.w, r32.w);
    t.p23[12] = make_float2(r23.x, r33.x); t.p23[13] = make_float2(r23.y, r33.y);
    t.p23[14] = make_float2(r23.z, r33.z); t.p23[15] = make_float2(r23.w, r33.w);
    return t;
}

// ---------------------------------------------------------------------------
// Kernel 3: logits + log_softmax. One CTA per s, 320 threads, 4 rows/thread,
// 25 chunks of 1280 rows. Pass 1 accumulates sum-of-exp per (b, thread) in
// padded shared memory (no big register arrays). Pass 2 recomputes and writes.
// ---------------------------------------------------------------------------
__global__ void __launch_bounds__(320, 1) logits_kernel(const float* __restrict__ V,
                                                        float* __restrict__ out) {
    const int s   = blockIdx.x;
    const int tid = threadIdx.x;
    const float4* Vq = (const float4*)V;

    __shared__ float2 hd[BATCH][REC];      // {h,h} duplicated for f32x2 broadcast
    __shared__ float  sumsh[BATCH][321];   // padded: stride 321 -> conflict-free
    __shared__ float  logZ[BATCH];

    for (int i = tid; i < BATCH * REC; i += 320) {
        float v = g_hidden[s * 512 + i];
        hd[i >> 4][i & (REC - 1)] = make_float2(v, v);
    }
#pragma unroll
    for (int b = 0; b < BATCH; b++) sumsh[b][tid] = 0.0f;
    __syncthreads();

    // ---------------- pass 1: sum of exp(logit) --------------------------
    for (int c = 0; c < 25; c++) {
        int v0 = c * 1280 + tid * 4;
        VTile t = load_vtile(Vq, v0);
#pragma unroll 4
        for (int b = 0; b < BATCH; b++) {
            float2 a01 = make_float2(0.f, 0.f), a23 = make_float2(0.f, 0.f);
#pragma unroll
            for (int j = 0; j < REC; j++) {
                float2 h2 = hd[b][j];                 // broadcast LDS.64
                a01 = ffma2(h2, t.p01[j], a01);
                a23 = ffma2(h2, t.p23[j], a23);
            }
            float e = (__expf(a01.x) + __expf(a01.y)) +
                      (__expf(a23.x) + __expf(a23.y));
            sumsh[b][tid] += e;
        }
    }
    __syncthreads();

    // ---------------- reduce -> logZ[b] ----------------------------------
    if (tid < BATCH) {
        float tot = 0.f;
        for (int w = 0; w < 320; w++) tot += sumsh[tid][w];
        logZ[tid] = __logf(tot);
    }
    __syncthreads();

    // ---------------- pass 2: recompute logits, write --------------------
    for (int c = 0; c < 25; c++) {
        int v0 = c * 1280 + tid * 4;
        VTile t = load_vtile(Vq, v0);
        float* obase = out + ((size_t)s * BATCH) * VOCAB + v0;
#pragma unroll 4
        for (int b = 0; b < BATCH; b++) {
            float2 a01 = make_float2(0.f, 0.f), a23 = make_float2(0.f, 0.f);
#pragma unroll
            for (int j = 0; j < REC; j++) {
                float2 h2 = hd[b][j];
                a01 = ffma2(h2, t.p01[j], a01);
                a23 = ffma2(h2, t.p23[j], a23);
            }
            float z = logZ[b];
            float4 o = make_float4(a01.x - z, a01.y - z, a23.x - z, a23.y - z);
            *(float4*)(obase + (size_t)b * VOCAB) = o;
        }
    }
}

// ---------------------------------------------------------------------------
extern "C" void kernel_launch(void* const* d_in, const int* in_sizes, int n_in,
                              void* d_out, int out_size) {
    const int*   tok = (const int*)  d_in[0];   // input_batch [SEQ, BATCH] int32
    const float* emb = (const float*)d_in[1];   // embedding   [VOCAB, EMB]
    const float* U   = (const float*)d_in[2];   // U [REC, EMB]
    const float* W   = (const float*)d_in[3];   // W [REC, REC]
    const float* V   = (const float*)d_in[4];   // V [VOCAB, REC]
    const float* b1  = (const float*)d_in[5];   // bias_1 [REC]
    const float* b2  = (const float*)d_in[6];   // bias_2 [REC]
    const float* h0  = (const float*)d_in[7];   // h0 [REC]
    float* out = (float*)d_out;                 // [SEQ, BATCH, VOCAB] f32

    iproj_kernel<<<(SEQ * BATCH * REC + 255) / 256, 256>>>(tok, emb, U, b1, b2);
    rnn_kernel<<<1, 256>>>(W, h0);
    logits_kernel<<<SEQ, 320>>>(V, out);
}

// round 4
// speedup vs baseline: 5.9574x; 1.3476x over previous
#include <cuda_runtime.h>
#include <cstddef>

#define VOCAB 32000
#define EMB   32
#define REC   16
#define SEQ   256
#define BATCH 32

#define VSLICES 5            // vocab slices per s
#define ROWS_PER_CTA (VOCAB / VSLICES)   // 6400
#define CHUNK 1280           // 320 threads * 4 rows
#define NCHUNK (ROWS_PER_CTA / CHUNK)    // 5

// Scratch (allocation-free rule: __device__ globals)
__device__ float g_hidden[SEQ * BATCH * REC];   // hidden[s][b][r]
__device__ float g_iproj [SEQ * BATCH * REC];   // x_t@U^T + b1 + b2
__device__ float g_sumexp[SEQ * BATCH];         // per (s,b) sum of exp(logit)
__device__ float g_Vp    [VOCAB * REC];         // V pre-paired for f32x2

// Packed f32x2 FMA (Blackwell; ptxas won't auto-fuse — PTX only)
__device__ __forceinline__ float2 ffma2(float2 a, float2 b, float2 c) {
    union { float2 f; unsigned long long u; } A, B, C, D;
    A.f = a; B.f = b; C.f = c;
    asm("fma.rn.f32x2 %0, %1, %2, %3;" : "=l"(D.u) : "l"(A.u), "l"(B.u), "l"(C.u));
    return D.f;
}

// ---------------------------------------------------------------------------
// Kernel 0: repack V into f32x2-pair tiles.
// Group g = 4 consecutive rows. Output block of 64 floats:
//   [0:32)  = interleave(row 4g,   row 4g+1) over j     -> p01 pairs
//   [32:64) = interleave(row 4g+2, row 4g+3) over j     -> p23 pairs
// ---------------------------------------------------------------------------
__global__ void vprep_kernel(const float* __restrict__ V) {
    int idx = blockIdx.x * blockDim.x + threadIdx.x;
    if (idx >= VOCAB * REC) return;
    int g = idx >> 6, o = idx & 63;
    int half = o >> 5, rem = o & 31;
    int j = rem >> 1, l = rem & 1;
    g_Vp[idx] = V[(size_t)(4 * g + 2 * half + l) * REC + j];
}

// ---------------------------------------------------------------------------
// Kernel 1: input projection + zero g_sumexp.
// ---------------------------------------------------------------------------
__global__ void iproj_kernel(const int* __restrict__ tok,
                             const float* __restrict__ emb,
                             const float* __restrict__ U,
                             const float* __restrict__ b1,
                             const float* __restrict__ b2) {
    int idx = blockIdx.x * blockDim.x + threadIdx.x;   // s*512 + b*16 + r
    if (idx < SEQ * BATCH) g_sumexp[idx] = 0.0f;
    if (idx >= SEQ * BATCH * REC) return;
    int r  = idx & (REC - 1);
    int sb = idx >> 4;
    int t  = tok[sb];
    const float4* e = (const float4*)(emb + (size_t)t * EMB);
    const float4* u = (const float4*)(U + (size_t)r * EMB);
    float acc = b1[r] + b2[r];
#pragma unroll
    for (int q = 0; q < EMB / 4; q++) {
        float4 ev = e[q], uv = u[q];
        acc = fmaf(ev.x, uv.x, acc);
        acc = fmaf(ev.y, uv.y, acc);
        acc = fmaf(ev.z, uv.z, acc);
        acc = fmaf(ev.w, uv.w, acc);
    }
    g_iproj[idx] = acc;
}

// ---------------------------------------------------------------------------
// Kernel 2: sequential recurrence (single CTA), unchanged from R2.
// ---------------------------------------------------------------------------
__global__ void __launch_bounds__(256) rnn_kernel(const float* __restrict__ W,
                                                  const float* __restrict__ h0) {
    __shared__ float2 hd[2][REC][17];
    int tid = threadIdx.x;
    int bp  = tid >> 4;
    int r   = tid & (REC - 1);

    float2 wdup[REC];
#pragma unroll
    for (int j = 0; j < REC; j++) {
        float w = W[r * REC + j];
        wdup[j] = make_float2(w, w);
    }

    float c0 = h0[r], c1 = c0;
    hd[0][r][bp] = make_float2(c0, c1);
    __syncthreads();

    const int base = bp * 2 * REC + r;

    float ip0[2], ip1[2];
    ip0[0] = g_iproj[0 * 512 + base];  ip1[0] = g_iproj[0 * 512 + base + REC];
    ip0[1] = g_iproj[1 * 512 + base];  ip1[1] = g_iproj[1 * 512 + base + REC];

    for (int t = 0; t < SEQ; t++) {
        g_hidden[t * 512 + base]       = c0;
        g_hidden[t * 512 + base + REC] = c1;

        if (t < SEQ - 1) {
            int rb = t & 1, wb = rb ^ 1;
            float2 acc = make_float2(ip0[rb], ip1[rb]);
            if (t + 2 < SEQ) {
                ip0[rb] = g_iproj[(t + 2) * 512 + base];
                ip1[rb] = g_iproj[(t + 2) * 512 + base + REC];
            }
#pragma unroll
            for (int j = 0; j < REC; j++)
                acc = ffma2(hd[rb][j][bp], wdup[j], acc);
            float e0 = __expf(2.0f * acc.x);
            float e1 = __expf(2.0f * acc.y);
            c0 = 1.0f - __fdividef(2.0f, e0 + 1.0f);
            c1 = 1.0f - __fdividef(2.0f, e1 + 1.0f);
            hd[wb][r][bp] = make_float2(c0, c1);
        }
        __syncthreads();
    }
}

// ---------------------------------------------------------------------------
// V tile loader: 16 LDG.128 from the pre-paired layout. Zero packing MOVs:
// each float4 is two ready-made f32x2 operands.
// ---------------------------------------------------------------------------
struct VTile {
    float2 p01[REC];
    float2 p23[REC];
};

__device__ __forceinline__ VTile load_vtile(int v0) {
    const float4* q = (const float4*)(g_Vp + (size_t)v0 * REC);  // group = v0/4
    VTile t;
#pragma unroll
    for (int i = 0; i < 8; i++) {
        float4 a = q[i];
        t.p01[2 * i]     = make_float2(a.x, a.y);
        t.p01[2 * i + 1] = make_float2(a.z, a.w);
    }
#pragma unroll
    for (int i = 0; i < 8; i++) {
        float4 a = q[8 + i];
        t.p23[2 * i]     = make_float2(a.x, a.y);
        t.p23[2 * i + 1] = make_float2(a.z, a.w);
    }
    return t;
}

// ---------------------------------------------------------------------------
// Kernel 3a: partial sum of exp(logit). grid(VSLICES, SEQ), 320 threads.
// 4 rows/thread, 5 chunks/CTA, batch-PAIR inner loop -> 4 indep FFMA2 chains.
// Warp-reduced partials accumulated to g_sumexp via one atomicAdd per (CTA,b).
// ---------------------------------------------------------------------------
__global__ void __launch_bounds__(320, 2) sumexp_kernel() {
    const int slice = blockIdx.x;
    const int s     = blockIdx.y;
    const int tid   = threadIdx.x;
    const int wid   = tid >> 5, lane = tid & 31;

    __shared__ float2 hd[BATCH][REC];
    __shared__ float  wsum[10][BATCH];

    for (int i = tid; i < BATCH * REC; i += 320) {
        float v = g_hidden[s * 512 + i];
        hd[i >> 4][i & (REC - 1)] = make_float2(v, v);
    }
    for (int i = tid; i < 10 * BATCH; i += 320)
        ((float*)wsum)[i] = 0.0f;
    __syncthreads();

    for (int c = 0; c < NCHUNK; c++) {
        int v0 = slice * ROWS_PER_CTA + c * CHUNK + tid * 4;
        VTile t = load_vtile(v0);
#pragma unroll 2
        for (int bp = 0; bp < BATCH / 2; bp++) {
            const int b0 = 2 * bp, b1 = 2 * bp + 1;
            float2 a01_0 = make_float2(0.f, 0.f), a23_0 = make_float2(0.f, 0.f);
            float2 a01_1 = make_float2(0.f, 0.f), a23_1 = make_float2(0.f, 0.f);
#pragma unroll
            for (int j = 0; j < REC; j++) {
                float2 h0 = hd[b0][j];
                float2 h1 = hd[b1][j];
                a01_0 = ffma2(h0, t.p01[j], a01_0);
                a23_0 = ffma2(h0, t.p23[j], a23_0);
                a01_1 = ffma2(h1, t.p01[j], a01_1);
                a23_1 = ffma2(h1, t.p23[j], a23_1);
            }
            float e0 = (__expf(a01_0.x) + __expf(a01_0.y)) +
                       (__expf(a23_0.x) + __expf(a23_0.y));
            float e1 = (__expf(a01_1.x) + __expf(a01_1.y)) +
                       (__expf(a23_1.x) + __expf(a23_1.y));
#pragma unroll
            for (int off = 16; off; off >>= 1) {
                e0 += __shfl_xor_sync(0xffffffffu, e0, off);
                e1 += __shfl_xor_sync(0xffffffffu, e1, off);
            }
            if (lane == 0) {
                wsum[wid][b0] += e0;
                wsum[wid][b1] += e1;
            }
        }
    }
    __syncthreads();

    if (tid < BATCH) {
        float tot = 0.f;
#pragma unroll
        for (int w = 0; w < 10; w++) tot += wsum[w][tid];
        atomicAdd(&g_sumexp[s * BATCH + tid], tot);
    }
}

// ---------------------------------------------------------------------------
// Kernel 3b: recompute logits, write log_softmax. Same geometry as 3a.
// ---------------------------------------------------------------------------
__global__ void __launch_bounds__(320, 2) write_kernel(float* __restrict__ out) {
    const int slice = blockIdx.x;
    const int s     = blockIdx.y;
    const int tid   = threadIdx.x;

    __shared__ float2 hd[BATCH][REC];
    __shared__ float  logZ[BATCH];

    for (int i = tid; i < BATCH * REC; i += 320) {
        float v = g_hidden[s * 512 + i];
        hd[i >> 4][i & (REC - 1)] = make_float2(v, v);
    }
    if (tid < BATCH)
        logZ[tid] = __logf(g_sumexp[s * BATCH + tid]);
    __syncthreads();

    for (int c = 0; c < NCHUNK; c++) {
        int v0 = slice * ROWS_PER_CTA + c * CHUNK + tid * 4;
        VTile t = load_vtile(v0);
        float* obase = out + ((size_t)s * BATCH) * VOCAB + v0;
#pragma unroll 2
        for (int bp = 0; bp < BATCH / 2; bp++) {
            const int b0 = 2 * bp, b1 = 2 * bp + 1;
            float2 a01_0 = make_float2(0.f, 0.f), a23_0 = make_float2(0.f, 0.f);
            float2 a01_1 = make_float2(0.f, 0.f), a23_1 = make_float2(0.f, 0.f);
#pragma unroll
            for (int j = 0; j < REC; j++) {
                float2 h0 = hd[b0][j];
                float2 h1 = hd[b1][j];
                a01_0 = ffma2(h0, t.p01[j], a01_0);
                a23_0 = ffma2(h0, t.p23[j], a23_0);
                a01_1 = ffma2(h1, t.p01[j], a01_1);
                a23_1 = ffma2(h1, t.p23[j], a23_1);
            }
            float z0 = logZ[b0], z1 = logZ[b1];
            float4 o0 = make_float4(a01_0.x - z0, a01_0.y - z0,
                                    a23_0.x - z0, a23_0.y - z0);
            float4 o1 = make_float4(a01_1.x - z1, a01_1.y - z1,
                                    a23_1.x - z1, a23_1.y - z1);
            *(float4*)(obase + (size_t)b0 * VOCAB) = o0;
            *(float4*)(obase + (size_t)b1 * VOCAB) = o1;
        }
    }
}

// ---------------------------------------------------------------------------
extern "C" void kernel_launch(void* const* d_in, const int* in_sizes, int n_in,
                              void* d_out, int out_size) {
    const int*   tok = (const int*)  d_in[0];   // input_batch [SEQ, BATCH] int32
    const float* emb = (const float*)d_in[1];   // embedding   [VOCAB, EMB]
    const float* U   = (const float*)d_in[2];   // U [REC, EMB]
    const float* W   = (const float*)d_in[3];   // W [REC, REC]
    const float* V   = (const float*)d_in[4];   // V [VOCAB, REC]
    const float* b1  = (const float*)d_in[5];   // bias_1 [REC]
    const float* b2  = (const float*)d_in[6];   // bias_2 [REC]
    const float* h0  = (const float*)d_in[7];   // h0 [REC]
    float* out = (float*)d_out;                 // [SEQ, BATCH, VOCAB] f32

    vprep_kernel<<<(VOCAB * REC + 255) / 256, 256>>>(V);
    iproj_kernel<<<(SEQ * BATCH * REC + 255) / 256, 256>>>(tok, emb, U, b1, b2);
    rnn_kernel<<<1, 256>>>(W, h0);
    dim3 grid(VSLICES, SEQ);
    sumexp_kernel<<<grid, 320>>>();
    write_kernel<<<grid, 320>>>(out);
}

// round 5
// speedup vs baseline: 6.1671x; 1.0352x over previous
#include <cuda_runtime.h>
#include <cstddef>

#define VOCAB 32000
#define EMB   32
#define REC   16
#define SEQ   256
#define BATCH 32

#define VSLICES 25                       // one 1280-row chunk per CTA
#define CHUNK   1280                     // 320 threads * 4 rows

// Scratch (allocation-free rule: __device__ globals)
__device__ float g_hidden[SEQ * BATCH * REC];   // hidden[s][b][r]
__device__ float g_iproj [SEQ * BATCH * REC];   // x_t@U^T + b1 + b2
__device__ float g_sumexp[SEQ * BATCH];         // per (s,b) sum of exp(logit)
__device__ float g_Vp    [VOCAB * REC];         // V pre-paired for f32x2

// Packed f32x2 ops (Blackwell; ptxas won't auto-fuse — PTX only)
__device__ __forceinline__ float2 ffma2(float2 a, float2 b, float2 c) {
    union { float2 f; unsigned long long u; } A, B, C, D;
    A.f = a; B.f = b; C.f = c;
    asm("fma.rn.f32x2 %0, %1, %2, %3;" : "=l"(D.u) : "l"(A.u), "l"(B.u), "l"(C.u));
    return D.f;
}
__device__ __forceinline__ float2 fadd2(float2 a, float2 b) {
    union { float2 f; unsigned long long u; } A, B, D;
    A.f = a; B.f = b;
    asm("add.rn.f32x2 %0, %1, %2;" : "=l"(D.u) : "l"(A.u), "l"(B.u));
    return D.f;
}

// ---------------------------------------------------------------------------
// Kernel 0: repack V into f32x2-pair tiles (group g = 4 rows -> 64 floats:
// [0:32) interleave(rows 4g,4g+1), [32:64) interleave(rows 4g+2,4g+3)).
// ---------------------------------------------------------------------------
__global__ void vprep_kernel(const float* __restrict__ V) {
    int idx = blockIdx.x * blockDim.x + threadIdx.x;
    if (idx >= VOCAB * REC) return;
    int g = idx >> 6, o = idx & 63;
    int half = o >> 5, rem = o & 31;
    int j = rem >> 1, l = rem & 1;
    g_Vp[idx] = V[(size_t)(4 * g + 2 * half + l) * REC + j];
}

// ---------------------------------------------------------------------------
// Kernel 1: input projection + zero g_sumexp.
// ---------------------------------------------------------------------------
__global__ void iproj_kernel(const int* __restrict__ tok,
                             const float* __restrict__ emb,
                             const float* __restrict__ U,
                             const float* __restrict__ b1,
                             const float* __restrict__ b2) {
    int idx = blockIdx.x * blockDim.x + threadIdx.x;
    if (idx < SEQ * BATCH) g_sumexp[idx] = 0.0f;
    if (idx >= SEQ * BATCH * REC) return;
    int r  = idx & (REC - 1);
    int sb = idx >> 4;
    int t  = tok[sb];
    const float4* e = (const float4*)(emb + (size_t)t * EMB);
    const float4* u = (const float4*)(U + (size_t)r * EMB);
    float acc = b1[r] + b2[r];
#pragma unroll
    for (int q = 0; q < EMB / 4; q++) {
        float4 ev = e[q], uv = u[q];
        acc = fmaf(ev.x, uv.x, acc);
        acc = fmaf(ev.y, uv.y, acc);
        acc = fmaf(ev.z, uv.z, acc);
        acc = fmaf(ev.w, uv.w, acc);
    }
    g_iproj[idx] = acc;
}

// ---------------------------------------------------------------------------
// Kernel 2: sequential recurrence (single CTA), unchanged.
// ---------------------------------------------------------------------------
__global__ void __launch_bounds__(256) rnn_kernel(const float* __restrict__ W,
                                                  const float* __restrict__ h0) {
    __shared__ float2 hd[2][REC][17];
    int tid = threadIdx.x;
    int bp  = tid >> 4;
    int r   = tid & (REC - 1);

    float2 wdup[REC];
#pragma unroll
    for (int j = 0; j < REC; j++) {
        float w = W[r * REC + j];
        wdup[j] = make_float2(w, w);
    }

    float c0 = h0[r], c1 = c0;
    hd[0][r][bp] = make_float2(c0, c1);
    __syncthreads();

    const int base = bp * 2 * REC + r;

    float ip0[2], ip1[2];
    ip0[0] = g_iproj[0 * 512 + base];  ip1[0] = g_iproj[0 * 512 + base + REC];
    ip0[1] = g_iproj[1 * 512 + base];  ip1[1] = g_iproj[1 * 512 + base + REC];

    for (int t = 0; t < SEQ; t++) {
        g_hidden[t * 512 + base]       = c0;
        g_hidden[t * 512 + base + REC] = c1;

        if (t < SEQ - 1) {
            int rb = t & 1, wb = rb ^ 1;
            float2 acc = make_float2(ip0[rb], ip1[rb]);
            if (t + 2 < SEQ) {
                ip0[rb] = g_iproj[(t + 2) * 512 + base];
                ip1[rb] = g_iproj[(t + 2) * 512 + base + REC];
            }
#pragma unroll
            for (int j = 0; j < REC; j++)
                acc = ffma2(hd[rb][j][bp], wdup[j], acc);
            float e0 = __expf(2.0f * acc.x);
            float e1 = __expf(2.0f * acc.y);
            c0 = 1.0f - __fdividef(2.0f, e0 + 1.0f);
            c1 = 1.0f - __fdividef(2.0f, e1 + 1.0f);
            hd[wb][r][bp] = make_float2(c0, c1);
        }
        __syncthreads();
    }
}

// ---------------------------------------------------------------------------
// V tile: 16 LDG.128 from pre-paired layout — zero packing MOVs.
// ---------------------------------------------------------------------------
struct VTile {
    float2 p01[REC];
    float2 p23[REC];
};

__device__ __forceinline__ VTile load_vtile(int v0) {
    const float4* q = (const float4*)(g_Vp + (size_t)v0 * REC);
    VTile t;
#pragma unroll
    for (int i = 0; i < 8; i++) {
        float4 a = q[i];
        t.p01[2 * i]     = make_float2(a.x, a.y);
        t.p01[2 * i + 1] = make_float2(a.z, a.w);
    }
#pragma unroll
    for (int i = 0; i < 8; i++) {
        float4 a = q[8 + i];
        t.p23[2 * i]     = make_float2(a.x, a.y);
        t.p23[2 * i + 1] = make_float2(a.z, a.w);
    }
    return t;
}

// Build hd4[j][bp] = {h[2bp][j], h[2bp][j], h[2bp+1][j], h[2bp+1][j]}
// -> one LDS.128 broadcast feeds 4 FFMA2 in the inner loop.
__device__ __forceinline__ void build_hd4(float4 (*hd4)[16], int s, int tid) {
    if (tid < 256) {
        int bp = tid & 15, j = tid >> 4;
        float v0 = g_hidden[s * 512 + (2 * bp)     * REC + j];
        float v1 = g_hidden[s * 512 + (2 * bp + 1) * REC + j];
        hd4[j][bp] = make_float4(v0, v0, v1, v1);
    }
}

// ---------------------------------------------------------------------------
// Kernel 3a: partial sum of exp(logit). grid(25, SEQ), 320 thr, 1 chunk/CTA.
// Per-thread smem accumulators (padded, conflict-free); no SHFL in hot loop.
// ---------------------------------------------------------------------------
__global__ void __launch_bounds__(320, 2) sumexp_kernel() {
    const int slice = blockIdx.x;
    const int s     = blockIdx.y;
    const int tid   = threadIdx.x;

    __shared__ float4 hd4[REC][16];
    __shared__ float  ssum[320 * 33];     // [tid][b] stride 33 -> conflict-free
    __shared__ float  part[10][BATCH];

    build_hd4(hd4, s, tid);
#pragma unroll
    for (int b = 0; b < 33; b++) ssum[tid * 33 + b] = 0.0f;
    __syncthreads();

    const int v0 = slice * CHUNK + tid * 4;
    VTile t = load_vtile(v0);
    float* my = &ssum[tid * 33];

#pragma unroll 2
    for (int bp = 0; bp < BATCH / 2; bp++) {
        float2 a01_0 = make_float2(0.f, 0.f), a23_0 = make_float2(0.f, 0.f);
        float2 a01_1 = make_float2(0.f, 0.f), a23_1 = make_float2(0.f, 0.f);
#pragma unroll
        for (int j = 0; j < REC; j++) {
            float4 h4 = hd4[j][bp];                       // LDS.128 broadcast
            float2 h0 = make_float2(h4.x, h4.y);
            float2 h1 = make_float2(h4.z, h4.w);
            a01_0 = ffma2(h0, t.p01[j], a01_0);
            a23_0 = ffma2(h0, t.p23[j], a23_0);
            a01_1 = ffma2(h1, t.p01[j], a01_1);
            a23_1 = ffma2(h1, t.p23[j], a23_1);
        }
        float e0 = (__expf(a01_0.x) + __expf(a01_0.y)) +
                   (__expf(a23_0.x) + __expf(a23_0.y));
        float e1 = (__expf(a01_1.x) + __expf(a01_1.y)) +
                   (__expf(a23_1.x) + __expf(a23_1.y));
        my[2 * bp]     += e0;
        my[2 * bp + 1] += e1;
    }
    __syncthreads();

    // CTA reduce: 320 threads -> part[grp][b] -> 32 atomics
    {
        int b = tid & 31, grp = tid >> 5;        // grp 0..9
        float acc = 0.f;
#pragma unroll
        for (int r = 0; r < 32; r++)
            acc += ssum[(grp * 32 + r) * 33 + b];
        part[grp][b] = acc;
    }
    __syncthreads();
    if (tid < BATCH) {
        float tot = 0.f;
#pragma unroll
        for (int w = 0; w < 10; w++) tot += part[w][tid];
        atomicAdd(&g_sumexp[s * BATCH + tid], tot);
    }
}

// ---------------------------------------------------------------------------
// Kernel 3b: recompute logits, write log_softmax. Same geometry.
// ---------------------------------------------------------------------------
__global__ void __launch_bounds__(320, 2) write_kernel(float* __restrict__ out) {
    const int slice = blockIdx.x;
    const int s     = blockIdx.y;
    const int tid   = threadIdx.x;

    __shared__ float4 hd4[REC][16];
    __shared__ float2 negz[BATCH];        // {-logZ, -logZ}

    build_hd4(hd4, s, tid);
    if (tid < BATCH) {
        float z = -__logf(g_sumexp[s * BATCH + tid]);
        negz[tid] = make_float2(z, z);
    }
    __syncthreads();

    const int v0 = slice * CHUNK + tid * 4;
    VTile t = load_vtile(v0);
    float* obase = out + ((size_t)s * BATCH) * VOCAB + v0;

#pragma unroll 2
    for (int bp = 0; bp < BATCH / 2; bp++) {
        float2 a01_0 = make_float2(0.f, 0.f), a23_0 = make_float2(0.f, 0.f);
        float2 a01_1 = make_float2(0.f, 0.f), a23_1 = make_float2(0.f, 0.f);
#pragma unroll
        for (int j = 0; j < REC; j++) {
            float4 h4 = hd4[j][bp];
            float2 h0 = make_float2(h4.x, h4.y);
            float2 h1 = make_float2(h4.z, h4.w);
            a01_0 = ffma2(h0, t.p01[j], a01_0);
            a23_0 = ffma2(h0, t.p23[j], a23_0);
            a01_1 = ffma2(h1, t.p01[j], a01_1);
            a23_1 = ffma2(h1, t.p23[j], a23_1);
        }
        float2 z0 = negz[2 * bp], z1 = negz[2 * bp + 1];
        a01_0 = fadd2(a01_0, z0);  a23_0 = fadd2(a23_0, z0);
        a01_1 = fadd2(a01_1, z1);  a23_1 = fadd2(a23_1, z1);
        float4 o0 = make_float4(a01_0.x, a01_0.y, a23_0.x, a23_0.y);
        float4 o1 = make_float4(a01_1.x, a01_1.y, a23_1.x, a23_1.y);
        *(float4*)(obase + (size_t)(2 * bp)     * VOCAB) = o0;
        *(float4*)(obase + (size_t)(2 * bp + 1) * VOCAB) = o1;
    }
}

// ---------------------------------------------------------------------------
extern "C" void kernel_launch(void* const* d_in, const int* in_sizes, int n_in,
                              void* d_out, int out_size) {
    const int*   tok = (const int*)  d_in[0];
    const float* emb = (const float*)d_in[1];
    const float* U   = (const float*)d_in[2];
    const float* W   = (const float*)d_in[3];
    const float* V   = (const float*)d_in[4];
    const float* b1  = (const float*)d_in[5];
    const float* b2  = (const float*)d_in[6];
    const float* h0  = (const float*)d_in[7];
    float* out = (float*)d_out;

    vprep_kernel<<<(VOCAB * REC + 255) / 256, 256>>>(V);
    iproj_kernel<<<(SEQ * BATCH * REC + 255) / 256, 256>>>(tok, emb, U, b1, b2);
    rnn_kernel<<<1, 256>>>(W, h0);
    dim3 grid(VSLICES, SEQ);
    sumexp_kernel<<<grid, 320>>>();
    write_kernel<<<grid, 320>>>(out);
}

// round 6
// speedup vs baseline: 6.1859x; 1.0031x over previous
#include <cuda_runtime.h>
#include <cstddef>

#define VOCAB 32000
#define EMB   32
#define REC   16
#define SEQ   256
#define BATCH 32

#define VSLICES 25                 // 25 slices of 1280 rows
#define CHUNK   1280               // 160 threads * 8 rows
#define NTHR    160

// Scratch (allocation-free rule: __device__ globals)
__device__ float g_hidden[SEQ * BATCH * REC];
__device__ float g_iproj [SEQ * BATCH * REC];
__device__ float g_sumexp[SEQ * BATCH];
__device__ float g_Vp    [VOCAB * REC];   // V pre-paired, groups of 8 rows

// Packed f32x2 ops (PTX only — ptxas won't auto-fuse)
__device__ __forceinline__ float2 ffma2(float2 a, float2 b, float2 c) {
    union { float2 f; unsigned long long u; } A, B, C, D;
    A.f = a; B.f = b; C.f = c;
    asm("fma.rn.f32x2 %0, %1, %2, %3;" : "=l"(D.u) : "l"(A.u), "l"(B.u), "l"(C.u));
    return D.f;
}
__device__ __forceinline__ float2 fadd2(float2 a, float2 b) {
    union { float2 f; unsigned long long u; } A, B, D;
    A.f = a; B.f = b;
    asm("add.rn.f32x2 %0, %1, %2;" : "=l"(D.u) : "l"(A.u), "l"(B.u));
    return D.f;
}

// ---------------------------------------------------------------------------
// Kernel 0: repack V. Group g = 8 rows -> 128-float block; quarter q=0..3
// holds interleave(rows 8g+2q, 8g+2q+1) over j: pos = q*32 + 2*j + l.
// ---------------------------------------------------------------------------
__global__ void vprep_kernel(const float* __restrict__ V) {
    int idx = blockIdx.x * blockDim.x + threadIdx.x;
    if (idx >= VOCAB * REC) return;
    int g = idx >> 7, o = idx & 127;
    int q = o >> 5, rem = o & 31;
    int j = rem >> 1, l = rem & 1;
    g_Vp[idx] = V[(size_t)(8 * g + 2 * q + l) * REC + j];
}

// ---------------------------------------------------------------------------
// Kernel 1: input projection + zero g_sumexp.
// ---------------------------------------------------------------------------
__global__ void iproj_kernel(const int* __restrict__ tok,
                             const float* __restrict__ emb,
                             const float* __restrict__ U,
                             const float* __restrict__ b1,
                             const float* __restrict__ b2) {
    int idx = blockIdx.x * blockDim.x + threadIdx.x;
    if (idx < SEQ * BATCH) g_sumexp[idx] = 0.0f;
    if (idx >= SEQ * BATCH * REC) return;
    int r  = idx & (REC - 1);
    int sb = idx >> 4;
    int t  = tok[sb];
    const float4* e = (const float4*)(emb + (size_t)t * EMB);
    const float4* u = (const float4*)(U + (size_t)r * EMB);
    float acc = b1[r] + b2[r];
#pragma unroll
    for (int q = 0; q < EMB / 4; q++) {
        float4 ev = e[q], uv = u[q];
        acc = fmaf(ev.x, uv.x, acc);
        acc = fmaf(ev.y, uv.y, acc);
        acc = fmaf(ev.z, uv.z, acc);
        acc = fmaf(ev.w, uv.w, acc);
    }
    g_iproj[idx] = acc;
}

// ---------------------------------------------------------------------------
// Kernel 2: sequential recurrence (single CTA), unchanged.
// ---------------------------------------------------------------------------
__global__ void __launch_bounds__(256) rnn_kernel(const float* __restrict__ W,
                                                  const float* __restrict__ h0) {
    __shared__ float2 hd[2][REC][17];
    int tid = threadIdx.x;
    int bp  = tid >> 4;
    int r   = tid & (REC - 1);

    float2 wdup[REC];
#pragma unroll
    for (int j = 0; j < REC; j++) {
        float w = W[r * REC + j];
        wdup[j] = make_float2(w, w);
    }

    float c0 = h0[r], c1 = c0;
    hd[0][r][bp] = make_float2(c0, c1);
    __syncthreads();

    const int base = bp * 2 * REC + r;

    float ip0[2], ip1[2];
    ip0[0] = g_iproj[0 * 512 + base];  ip1[0] = g_iproj[0 * 512 + base + REC];
    ip0[1] = g_iproj[1 * 512 + base];  ip1[1] = g_iproj[1 * 512 + base + REC];

    for (int t = 0; t < SEQ; t++) {
        g_hidden[t * 512 + base]       = c0;
        g_hidden[t * 512 + base + REC] = c1;

        if (t < SEQ - 1) {
            int rb = t & 1, wb = rb ^ 1;
            float2 acc = make_float2(ip0[rb], ip1[rb]);
            if (t + 2 < SEQ) {
                ip0[rb] = g_iproj[(t + 2) * 512 + base];
                ip1[rb] = g_iproj[(t + 2) * 512 + base + REC];
            }
#pragma unroll
            for (int j = 0; j < REC; j++)
                acc = ffma2(hd[rb][j][bp], wdup[j], acc);
            float e0 = __expf(2.0f * acc.x);
            float e1 = __expf(2.0f * acc.y);
            c0 = 1.0f - __fdividef(2.0f, e0 + 1.0f);
            c1 = 1.0f - __fdividef(2.0f, e1 + 1.0f);
            hd[wb][r][bp] = make_float2(c0, c1);
        }
        __syncthreads();
    }
}

// ---------------------------------------------------------------------------
// V tile: 8 rows/thread as 4 row-pair lanes x 16 j. 32 LDG.128, zero MOVs.
// ---------------------------------------------------------------------------
struct VTile8 {
    float2 p[4][REC];    // p[q][j] = {V[v0+2q][j], V[v0+2q+1][j]}
};

__device__ __forceinline__ VTile8 load_vtile8(int v0) {
    const float4* q4 = (const float4*)(g_Vp + (size_t)v0 * REC);
    VTile8 t;
#pragma unroll
    for (int q = 0; q < 4; q++) {
#pragma unroll
        for (int i = 0; i < 8; i++) {
            float4 a = q4[q * 8 + i];
            t.p[q][2 * i]     = make_float2(a.x, a.y);
            t.p[q][2 * i + 1] = make_float2(a.z, a.w);
        }
    }
    return t;
}

// ---------------------------------------------------------------------------
// Kernel 3a: partial sum of exp(logit). grid(25, SEQ), 160 thr, 8 rows/thr.
// h via LDS.32 broadcast (1 crossbar-cyc) + reg duplication; 8 FFMA2 per
// h-load pair -> fma-bound with 2x L1 headroom.
// ---------------------------------------------------------------------------
__global__ void __launch_bounds__(NTHR, 2) sumexp_kernel() {
    const int slice = blockIdx.x;
    const int s     = blockIdx.y;
    const int tid   = threadIdx.x;

    __shared__ float hs[BATCH * REC];          // h[b][j], scalar broadcast reads
    __shared__ float ssum[NTHR * 33];          // [tid][b] padded
    __shared__ float part[5][BATCH];

    for (int i = tid; i < BATCH * REC; i += NTHR)
        hs[i] = g_hidden[s * 512 + i];
#pragma unroll
    for (int b = 0; b < 33; b++) ssum[tid * 33 + b] = 0.0f;
    __syncthreads();

    const int v0 = slice * CHUNK + tid * 8;
    VTile8 t = load_vtile8(v0);
    float* my = &ssum[tid * 33];

#pragma unroll 2
    for (int bp = 0; bp < BATCH / 2; bp++) {
        float2 a0[4], a1[4];
#pragma unroll
        for (int q = 0; q < 4; q++) {
            a0[q] = make_float2(0.f, 0.f);
            a1[q] = make_float2(0.f, 0.f);
        }
#pragma unroll
        for (int j = 0; j < REC; j++) {
            float h0 = hs[(2 * bp)     * REC + j];   // LDS.32 broadcast
            float h1 = hs[(2 * bp + 1) * REC + j];
            float2 h0p = make_float2(h0, h0);        // 1 MOV (alu pipe)
            float2 h1p = make_float2(h1, h1);
#pragma unroll
            for (int q = 0; q < 4; q++) {
                a0[q] = ffma2(h0p, t.p[q][j], a0[q]);
                a1[q] = ffma2(h1p, t.p[q][j], a1[q]);
            }
        }
        float e0 = 0.f, e1 = 0.f;
#pragma unroll
        for (int q = 0; q < 4; q++) {
            e0 += __expf(a0[q].x) + __expf(a0[q].y);
            e1 += __expf(a1[q].x) + __expf(a1[q].y);
        }
        my[2 * bp]     += e0;
        my[2 * bp + 1] += e1;
    }
    __syncthreads();

    // CTA reduce: 160 threads -> part[5][32] -> 32 atomics
    {
        int b = tid & 31, grp = tid >> 5;    // grp 0..4
        float acc = 0.f;
#pragma unroll
        for (int r = 0; r < 32; r++)
            acc += ssum[(grp * 32 + r) * 33 + b];
        part[grp][b] = acc;
    }
    __syncthreads();
    if (tid < BATCH) {
        float tot = 0.f;
#pragma unroll
        for (int w = 0; w < 5; w++) tot += part[w][tid];
        atomicAdd(&g_sumexp[s * BATCH + tid], tot);
    }
}

// ---------------------------------------------------------------------------
// Kernel 3b: recompute logits, write log_softmax. Same geometry.
// ---------------------------------------------------------------------------
__global__ void __launch_bounds__(NTHR, 2) write_kernel(float* __restrict__ out) {
    const int slice = blockIdx.x;
    const int s     = blockIdx.y;
    const int tid   = threadIdx.x;

    __shared__ float hs[BATCH * REC];
    __shared__ float nz[BATCH];              // -logZ

    for (int i = tid; i < BATCH * REC; i += NTHR)
        hs[i] = g_hidden[s * 512 + i];
    if (tid < BATCH)
        nz[tid] = -__logf(g_sumexp[s * BATCH + tid]);
    __syncthreads();

    const int v0 = slice * CHUNK + tid * 8;
    VTile8 t = load_vtile8(v0);
    float* obase = out + ((size_t)s * BATCH) * VOCAB + v0;

#pragma unroll 2
    for (int bp = 0; bp < BATCH / 2; bp++) {
        float2 a0[4], a1[4];
#pragma unroll
        for (int q = 0; q < 4; q++) {
            a0[q] = make_float2(0.f, 0.f);
            a1[q] = make_float2(0.f, 0.f);
        }
#pragma unroll
        for (int j = 0; j < REC; j++) {
            float h0 = hs[(2 * bp)     * REC + j];
            float h1 = hs[(2 * bp + 1) * REC + j];
            float2 h0p = make_float2(h0, h0);
            float2 h1p = make_float2(h1, h1);
#pragma unroll
            for (int q = 0; q < 4; q++) {
                a0[q] = ffma2(h0p, t.p[q][j], a0[q]);
                a1[q] = ffma2(h1p, t.p[q][j], a1[q]);
            }
        }
        float z0 = nz[2 * bp], z1 = nz[2 * bp + 1];
        float2 z0p = make_float2(z0, z0), z1p = make_float2(z1, z1);
#pragma unroll
        for (int q = 0; q < 4; q++) {
            a0[q] = fadd2(a0[q], z0p);
            a1[q] = fadd2(a1[q], z1p);
        }
        float* o0 = obase + (size_t)(2 * bp)     * VOCAB;
        float* o1 = obase + (size_t)(2 * bp + 1) * VOCAB;
        *(float4*)(o0)     = make_float4(a0[0].x, a0[0].y, a0[1].x, a0[1].y);
        *(float4*)(o0 + 4) = make_float4(a0[2].x, a0[2].y, a0[3].x, a0[3].y);
        *(float4*)(o1)     = make_float4(a1[0].x, a1[0].y, a1[1].x, a1[1].y);
        *(float4*)(o1 + 4) = make_float4(a1[2].x, a1[2].y, a1[3].x, a1[3].y);
    }
}

// ---------------------------------------------------------------------------
extern "C" void kernel_launch(void* const* d_in, const int* in_sizes, int n_in,
                              void* d_out, int out_size) {
    const int*   tok = (const int*)  d_in[0];
    const float* emb = (const float*)d_in[1];
    const float* U   = (const float*)d_in[2];
    const float* W   = (const float*)d_in[3];
    const float* V   = (const float*)d_in[4];
    const float* b1  = (const float*)d_in[5];
    const float* b2  = (const float*)d_in[6];
    const float* h0  = (const float*)d_in[7];
    float* out = (float*)d_out;

    vprep_kernel<<<(VOCAB * REC + 255) / 256, 256>>>(V);
    iproj_kernel<<<(SEQ * BATCH * REC + 255) / 256, 256>>>(tok, emb, U, b1, b2);
    rnn_kernel<<<1, 256>>>(W, h0);
    dim3 grid(VSLICES, SEQ);
    sumexp_kernel<<<grid, NTHR>>>();
    write_kernel<<<grid, NTHR>>>(out);
}

// round 7
// speedup vs baseline: 7.0799x; 1.1445x over previous
#include <cuda_runtime.h>
#include <cstddef>

#define VOCAB 32000
#define EMB   32
#define REC   16
#define SEQ   256
#define BATCH 32

#define NTHR    160
#define ROWS    4
#define CHUNK   (NTHR * ROWS)          // 640
#define VSLICES (VOCAB / CHUNK)        // 50

// Scratch (allocation-free rule: __device__ globals)
__device__ float g_hidden[SEQ * BATCH * REC];
__device__ float g_iproj [SEQ * BATCH * REC];
__device__ float g_sumexp[SEQ * BATCH];
__device__ float g_Vp    [VOCAB * REC];   // V pre-paired, groups of 4 rows

// Packed f32x2 ops (PTX only — ptxas won't auto-fuse)
__device__ __forceinline__ float2 ffma2(float2 a, float2 b, float2 c) {
    union { float2 f; unsigned long long u; } A, B, C, D;
    A.f = a; B.f = b; C.f = c;
    asm("fma.rn.f32x2 %0, %1, %2, %3;" : "=l"(D.u) : "l"(A.u), "l"(B.u), "l"(C.u));
    return D.f;
}
__device__ __forceinline__ float2 fadd2(float2 a, float2 b) {
    union { float2 f; unsigned long long u; } A, B, D;
    A.f = a; B.f = b;
    asm("add.rn.f32x2 %0, %1, %2;" : "=l"(D.u) : "l"(A.u), "l"(B.u));
    return D.f;
}

// ---------------------------------------------------------------------------
// Kernel 0: repack V. Group g = 4 rows -> 64 floats:
// [0:32) interleave(rows 4g,4g+1) over j; [32:64) interleave(rows 4g+2,4g+3).
// ---------------------------------------------------------------------------
__global__ void vprep_kernel(const float* __restrict__ V) {
    int idx = blockIdx.x * blockDim.x + threadIdx.x;
    if (idx >= VOCAB * REC) return;
    int g = idx >> 6, o = idx & 63;
    int half = o >> 5, rem = o & 31;
    int j = rem >> 1, l = rem & 1;
    g_Vp[idx] = V[(size_t)(4 * g + 2 * half + l) * REC + j];
}

// ---------------------------------------------------------------------------
// Kernel 1: input projection + zero g_sumexp.
// ---------------------------------------------------------------------------
__global__ void iproj_kernel(const int* __restrict__ tok,
                             const float* __restrict__ emb,
                             const float* __restrict__ U,
                             const float* __restrict__ b1,
                             const float* __restrict__ b2) {
    int idx = blockIdx.x * blockDim.x + threadIdx.x;
    if (idx < SEQ * BATCH) g_sumexp[idx] = 0.0f;
    if (idx >= SEQ * BATCH * REC) return;
    int r  = idx & (REC - 1);
    int sb = idx >> 4;
    int t  = tok[sb];
    const float4* e = (const float4*)(emb + (size_t)t * EMB);
    const float4* u = (const float4*)(U + (size_t)r * EMB);
    float acc = b1[r] + b2[r];
#pragma unroll
    for (int q = 0; q < EMB / 4; q++) {
        float4 ev = e[q], uv = u[q];
        acc = fmaf(ev.x, uv.x, acc);
        acc = fmaf(ev.y, uv.y, acc);
        acc = fmaf(ev.z, uv.z, acc);
        acc = fmaf(ev.w, uv.w, acc);
    }
    g_iproj[idx] = acc;
}

// ---------------------------------------------------------------------------
// Kernel 2: sequential recurrence (single CTA), unchanged.
// ---------------------------------------------------------------------------
__global__ void __launch_bounds__(256) rnn_kernel(const float* __restrict__ W,
                                                  const float* __restrict__ h0) {
    __shared__ float2 hd[2][REC][17];
    int tid = threadIdx.x;
    int bp  = tid >> 4;
    int r   = tid & (REC - 1);

    float2 wdup[REC];
#pragma unroll
    for (int j = 0; j < REC; j++) {
        float w = W[r * REC + j];
        wdup[j] = make_float2(w, w);
    }

    float c0 = h0[r], c1 = c0;
    hd[0][r][bp] = make_float2(c0, c1);
    __syncthreads();

    const int base = bp * 2 * REC + r;

    float ip0[2], ip1[2];
    ip0[0] = g_iproj[0 * 512 + base];  ip1[0] = g_iproj[0 * 512 + base + REC];
    ip0[1] = g_iproj[1 * 512 + base];  ip1[1] = g_iproj[1 * 512 + base + REC];

    for (int t = 0; t < SEQ; t++) {
        g_hidden[t * 512 + base]       = c0;
        g_hidden[t * 512 + base + REC] = c1;

        if (t < SEQ - 1) {
            int rb = t & 1, wb = rb ^ 1;
            float2 acc = make_float2(ip0[rb], ip1[rb]);
            if (t + 2 < SEQ) {
                ip0[rb] = g_iproj[(t + 2) * 512 + base];
                ip1[rb] = g_iproj[(t + 2) * 512 + base + REC];
            }
#pragma unroll
            for (int j = 0; j < REC; j++)
                acc = ffma2(hd[rb][j][bp], wdup[j], acc);
            float e0 = __expf(2.0f * acc.x);
            float e1 = __expf(2.0f * acc.y);
            c0 = 1.0f - __fdividef(2.0f, e0 + 1.0f);
            c1 = 1.0f - __fdividef(2.0f, e1 + 1.0f);
            hd[wb][r][bp] = make_float2(c0, c1);
        }
        __syncthreads();
    }
}

// ---------------------------------------------------------------------------
// V tile: 4 rows/thread as 2 row-pair lanes x 16 j. 16 LDG.128, zero MOVs.
// ---------------------------------------------------------------------------
struct VTile4 {
    float2 p01[REC];   // {V[v0+0][j], V[v0+1][j]}
    float2 p23[REC];   // {V[v0+2][j], V[v0+3][j]}
};

__device__ __forceinline__ VTile4 load_vtile4(int v0) {
    const float4* q4 = (const float4*)(g_Vp + (size_t)v0 * REC);
    VTile4 t;
#pragma unroll
    for (int i = 0; i < 8; i++) {
        float4 a = q4[i];
        t.p01[2 * i]     = make_float2(a.x, a.y);
        t.p01[2 * i + 1] = make_float2(a.z, a.w);
    }
#pragma unroll
    for (int i = 0; i < 8; i++) {
        float4 a = q4[8 + i];
        t.p23[2 * i]     = make_float2(a.x, a.y);
        t.p23[2 * i + 1] = make_float2(a.z, a.w);
    }
    return t;
}

// ---------------------------------------------------------------------------
// Kernel 3a: partial sum of exp(logit). grid(50, SEQ), 160 thr, 4 rows/thr,
// 4-batch inner block: per j, 4 LDS.32 + 4 MOV feed 8 FFMA2. ~100 regs ->
// 4 CTAs/SM = 20 warps.
// ---------------------------------------------------------------------------
__global__ void __launch_bounds__(NTHR, 4) sumexp_kernel() {
    const int slice = blockIdx.x;
    const int s     = blockIdx.y;
    const int tid   = threadIdx.x;

    __shared__ float hs[BATCH * REC];          // h[b][j]
    __shared__ float ssum[NTHR * 33];          // [tid][b] padded
    __shared__ float part[5][BATCH];

    for (int i = tid; i < BATCH * REC; i += NTHR)
        hs[i] = g_hidden[s * 512 + i];
#pragma unroll
    for (int b = 0; b < 33; b++) ssum[tid * 33 + b] = 0.0f;
    __syncthreads();

    const int v0 = slice * CHUNK + tid * ROWS;
    VTile4 t = load_vtile4(v0);
    float* my = &ssum[tid * 33];

#pragma unroll 2
    for (int q = 0; q < BATCH / 4; q++) {
        const int b0 = 4 * q;
        float2 aA0 = make_float2(0.f, 0.f), aA1 = make_float2(0.f, 0.f);
        float2 aB0 = make_float2(0.f, 0.f), aB1 = make_float2(0.f, 0.f);
        float2 aC0 = make_float2(0.f, 0.f), aC1 = make_float2(0.f, 0.f);
        float2 aD0 = make_float2(0.f, 0.f), aD1 = make_float2(0.f, 0.f);
#pragma unroll
        for (int j = 0; j < REC; j++) {
            float hA = hs[(b0 + 0) * REC + j];     // LDS.32 broadcast
            float hB = hs[(b0 + 1) * REC + j];
            float hC = hs[(b0 + 2) * REC + j];
            float hD = hs[(b0 + 3) * REC + j];
            float2 hAp = make_float2(hA, hA);
            float2 hBp = make_float2(hB, hB);
            float2 hCp = make_float2(hC, hC);
            float2 hDp = make_float2(hD, hD);
            aA0 = ffma2(hAp, t.p01[j], aA0);  aA1 = ffma2(hAp, t.p23[j], aA1);
            aB0 = ffma2(hBp, t.p01[j], aB0);  aB1 = ffma2(hBp, t.p23[j], aB1);
            aC0 = ffma2(hCp, t.p01[j], aC0);  aC1 = ffma2(hCp, t.p23[j], aC1);
            aD0 = ffma2(hDp, t.p01[j], aD0);  aD1 = ffma2(hDp, t.p23[j], aD1);
        }
        float eA = (__expf(aA0.x) + __expf(aA0.y)) + (__expf(aA1.x) + __expf(aA1.y));
        float eB = (__expf(aB0.x) + __expf(aB0.y)) + (__expf(aB1.x) + __expf(aB1.y));
        float eC = (__expf(aC0.x) + __expf(aC0.y)) + (__expf(aC1.x) + __expf(aC1.y));
        float eD = (__expf(aD0.x) + __expf(aD0.y)) + (__expf(aD1.x) + __expf(aD1.y));
        my[b0 + 0] += eA;
        my[b0 + 1] += eB;
        my[b0 + 2] += eC;
        my[b0 + 3] += eD;
    }
    __syncthreads();

    // CTA reduce: 160 threads -> part[5][32] -> 32 atomics
    {
        int b = tid & 31, grp = tid >> 5;    // grp 0..4
        float acc = 0.f;
#pragma unroll
        for (int r = 0; r < 32; r++)
            acc += ssum[(grp * 32 + r) * 33 + b];
        part[grp][b] = acc;
    }
    __syncthreads();
    if (tid < BATCH) {
        float tot = 0.f;
#pragma unroll
        for (int w = 0; w < 5; w++) tot += part[w][tid];
        atomicAdd(&g_sumexp[s * BATCH + tid], tot);
    }
}

// ---------------------------------------------------------------------------
// Kernel 3b: recompute logits, write log_softmax. Same geometry.
// ---------------------------------------------------------------------------
__global__ void __launch_bounds__(NTHR, 4) write_kernel(float* __restrict__ out) {
    const int slice = blockIdx.x;
    const int s     = blockIdx.y;
    const int tid   = threadIdx.x;

    __shared__ float hs[BATCH * REC];
    __shared__ float nz[BATCH];              // -logZ

    for (int i = tid; i < BATCH * REC; i += NTHR)
        hs[i] = g_hidden[s * 512 + i];
    if (tid < BATCH)
        nz[tid] = -__logf(g_sumexp[s * BATCH + tid]);
    __syncthreads();

    const int v0 = slice * CHUNK + tid * ROWS;
    VTile4 t = load_vtile4(v0);
    float* obase = out + ((size_t)s * BATCH) * VOCAB + v0;

#pragma unroll 2
    for (int q = 0; q < BATCH / 4; q++) {
        const int b0 = 4 * q;
        float2 aA0 = make_float2(0.f, 0.f), aA1 = make_float2(0.f, 0.f);
        float2 aB0 = make_float2(0.f, 0.f), aB1 = make_float2(0.f, 0.f);
        float2 aC0 = make_float2(0.f, 0.f), aC1 = make_float2(0.f, 0.f);
        float2 aD0 = make_float2(0.f, 0.f), aD1 = make_float2(0.f, 0.f);
#pragma unroll
        for (int j = 0; j < REC; j++) {
            float hA = hs[(b0 + 0) * REC + j];
            float hB = hs[(b0 + 1) * REC + j];
            float hC = hs[(b0 + 2) * REC + j];
            float hD = hs[(b0 + 3) * REC + j];
            float2 hAp = make_float2(hA, hA);
            float2 hBp = make_float2(hB, hB);
            float2 hCp = make_float2(hC, hC);
            float2 hDp = make_float2(hD, hD);
            aA0 = ffma2(hAp, t.p01[j], aA0);  aA1 = ffma2(hAp, t.p23[j], aA1);
            aB0 = ffma2(hBp, t.p01[j], aB0);  aB1 = ffma2(hBp, t.p23[j], aB1);
            aC0 = ffma2(hCp, t.p01[j], aC0);  aC1 = ffma2(hCp, t.p23[j], aC1);
            aD0 = ffma2(hDp, t.p01[j], aD0);  aD1 = ffma2(hDp, t.p23[j], aD1);
        }
        float zA = nz[b0 + 0], zB = nz[b0 + 1], zC = nz[b0 + 2], zD = nz[b0 + 3];
        float2 zAp = make_float2(zA, zA), zBp = make_float2(zB, zB);
        float2 zCp = make_float2(zC, zC), zDp = make_float2(zD, zD);
        aA0 = fadd2(aA0, zAp);  aA1 = fadd2(aA1, zAp);
        aB0 = fadd2(aB0, zBp);  aB1 = fadd2(aB1, zBp);
        aC0 = fadd2(aC0, zCp);  aC1 = fadd2(aC1, zCp);
        aD0 = fadd2(aD0, zDp);  aD1 = fadd2(aD1, zDp);
        *(float4*)(obase + (size_t)(b0 + 0) * VOCAB) =
            make_float4(aA0.x, aA0.y, aA1.x, aA1.y);
        *(float4*)(obase + (size_t)(b0 + 1) * VOCAB) =
            make_float4(aB0.x, aB0.y, aB1.x, aB1.y);
        *(float4*)(obase + (size_t)(b0 + 2) * VOCAB) =
            make_float4(aC0.x, aC0.y, aC1.x, aC1.y);
        *(float4*)(obase + (size_t)(b0 + 3) * VOCAB) =
            make_float4(aD0.x, aD0.y, aD1.x, aD1.y);
    }
}

// ---------------------------------------------------------------------------
extern "C" void kernel_launch(void* const* d_in, const int* in_sizes, int n_in,
                              void* d_out, int out_size) {
    const int*   tok = (const int*)  d_in[0];
    const float* emb = (const float*)d_in[1];
    const float* U   = (const float*)d_in[2];
    const float* W   = (const float*)d_in[3];
    const float* V   = (const float*)d_in[4];
    const float* b1  = (const float*)d_in[5];
    const float* b2  = (const float*)d_in[6];
    const float* h0  = (const float*)d_in[7];
    float* out = (float*)d_out;

    vprep_kernel<<<(VOCAB * REC + 255) / 256, 256>>>(V);
    iproj_kernel<<<(SEQ * BATCH * REC + 255) / 256, 256>>>(tok, emb, U, b1, b2);
    rnn_kernel<<<1, 256>>>(W, h0);
    dim3 grid(VSLICES, SEQ);
    sumexp_kernel<<<grid, NTHR>>>();
    write_kernel<<<grid, NTHR>>>(out);
}

// round 9
// speedup vs baseline: 13.4134x; 1.8946x over previous
#include <cuda_runtime.h>
#include <cuda_bf16.h>
#include <cstdint>
#include <cstddef>

#define VOCAB 32000
#define EMB   32
#define REC   16
#define SEQ   256
#define BATCH 32

#define NTILES        (VOCAB / 16)     // 2000 m16-tiles
#define SLICES        10
#define TILES_PER_CTA (NTILES / SLICES)        // 200
#define WARPS         8
#define TILES_PER_W   (TILES_PER_CTA / WARPS)  // 25

// Scratch (allocation-free rule: __device__ globals)
__device__ float g_hidden[SEQ * BATCH * REC];
__device__ float g_iproj [SEQ * BATCH * REC];
__device__ float g_sumexp[SEQ * BATCH];
__device__ uint4 g_Vmma  [NTILES * 32];   // A fragments, lane-ordered per tile

// ---------------------------------------------------------------------------
// helpers
// ---------------------------------------------------------------------------
__device__ __forceinline__ float2 ffma2(float2 a, float2 b, float2 c) {
    union { float2 f; unsigned long long u; } A, B, C, D;
    A.f = a; B.f = b; C.f = c;
    asm("fma.rn.f32x2 %0, %1, %2, %3;" : "=l"(D.u) : "l"(A.u), "l"(B.u), "l"(C.u));
    return D.f;
}

__device__ __forceinline__ uint32_t pk2(float a, float b) {
    __nv_bfloat162 t = __float22bfloat162_rn(make_float2(a, b));
    return *reinterpret_cast<uint32_t*>(&t);
}

// D(16x8) += A(16x16,bf16,row) * B(16x8,bf16,col)   — base-ISA HMMA
__device__ __forceinline__ void mma16816(float* d, const uint4& a,
                                         uint32_t b0, uint32_t b1) {
    asm volatile(
        "mma.sync.aligned.m16n8k16.row.col.f32.bf16.bf16.f32 "
        "{%0,%1,%2,%3}, {%4,%5,%6,%7}, {%8,%9}, {%0,%1,%2,%3};"
        : "+f"(d[0]), "+f"(d[1]), "+f"(d[2]), "+f"(d[3])
        : "r"(a.x), "r"(a.y), "r"(a.z), "r"(a.w), "r"(b0), "r"(b1));
}

// ---------------------------------------------------------------------------
// Kernel 0: pack V rows into mma A-fragment order.
// tile m-rows = [16*tile, 16*tile+16); lane (g = lane>>2, t = lane&3) holds:
//   a.x = {V[g][2t],V[g][2t+1]}  a.y = {V[g+8][2t],...}
//   a.z = {V[g][2t+8],...}       a.w = {V[g+8][2t+8],...}
// ---------------------------------------------------------------------------
__global__ void vprep_kernel(const float* __restrict__ V) {
    int idx = blockIdx.x * blockDim.x + threadIdx.x;
    if (idx >= NTILES * 32) return;
    int tile = idx >> 5, lane = idx & 31;
    int g = lane >> 2, t = lane & 3;
    const float* r0 = V + (size_t)(tile * 16 + g)     * REC;
    const float* r1 = V + (size_t)(tile * 16 + g + 8) * REC;
    uint4 a;
    a.x = pk2(r0[2 * t],     r0[2 * t + 1]);
    a.y = pk2(r1[2 * t],     r1[2 * t + 1]);
    a.z = pk2(r0[2 * t + 8], r0[2 * t + 9]);
    a.w = pk2(r1[2 * t + 8], r1[2 * t + 9]);
    g_Vmma[idx] = a;
}

// ---------------------------------------------------------------------------
// Kernel 1: input projection + zero g_sumexp.
// ---------------------------------------------------------------------------
__global__ void iproj_kernel(const int* __restrict__ tok,
                             const float* __restrict__ emb,
                             const float* __restrict__ U,
                             const float* __restrict__ b1,
                             const float* __restrict__ b2) {
    int idx = blockIdx.x * blockDim.x + threadIdx.x;
    if (idx < SEQ * BATCH) g_sumexp[idx] = 0.0f;
    if (idx >= SEQ * BATCH * REC) return;
    int r  = idx & (REC - 1);
    int sb = idx >> 4;
    int t  = tok[sb];
    const float4* e = (const float4*)(emb + (size_t)t * EMB);
    const float4* u = (const float4*)(U + (size_t)r * EMB);
    float acc = b1[r] + b2[r];
#pragma unroll
    for (int q = 0; q < EMB / 4; q++) {
        float4 ev = e[q], uv = u[q];
        acc = fmaf(ev.x, uv.x, acc);
        acc = fmaf(ev.y, uv.y, acc);
        acc = fmaf(ev.z, uv.z, acc);
        acc = fmaf(ev.w, uv.w, acc);
    }
    g_iproj[idx] = acc;
}

// ---------------------------------------------------------------------------
// Kernel 2: sequential recurrence (single CTA), unchanged.
// ---------------------------------------------------------------------------
__global__ void __launch_bounds__(256) rnn_kernel(const float* __restrict__ W,
                                                  const float* __restrict__ h0) {
    __shared__ float2 hd[2][REC][17];
    int tid = threadIdx.x;
    int bp  = tid >> 4;
    int r   = tid & (REC - 1);

    float2 wdup[REC];
#pragma unroll
    for (int j = 0; j < REC; j++) {
        float w = W[r * REC + j];
        wdup[j] = make_float2(w, w);
    }

    float c0 = h0[r], c1 = c0;
    hd[0][r][bp] = make_float2(c0, c1);
    __syncthreads();

    const int base = bp * 2 * REC + r;

    float ip0[2], ip1[2];
    ip0[0] = g_iproj[0 * 512 + base];  ip1[0] = g_iproj[0 * 512 + base + REC];
    ip0[1] = g_iproj[1 * 512 + base];  ip1[1] = g_iproj[1 * 512 + base + REC];

    for (int t = 0; t < SEQ; t++) {
        g_hidden[t * 512 + base]       = c0;
        g_hidden[t * 512 + base + REC] = c1;

        if (t < SEQ - 1) {
            int rb = t & 1, wb = rb ^ 1;
            float2 acc = make_float2(ip0[rb], ip1[rb]);
            if (t + 2 < SEQ) {
                ip0[rb] = g_iproj[(t + 2) * 512 + base];
                ip1[rb] = g_iproj[(t + 2) * 512 + base + REC];
            }
#pragma unroll
            for (int j = 0; j < REC; j++)
                acc = ffma2(hd[rb][j][bp], wdup[j], acc);
            float e0 = __expf(2.0f * acc.x);
            float e1 = __expf(2.0f * acc.y);
            c0 = 1.0f - __fdividef(2.0f, e0 + 1.0f);
            c1 = 1.0f - __fdividef(2.0f, e1 + 1.0f);
            hd[wb][r][bp] = make_float2(c0, c1);
        }
        __syncthreads();
    }
}

// Build B fragments for the 4 batch-chunks (n = 8c + g, k packs over t).
__device__ __forceinline__ void make_bfrags(uint32_t* B0, uint32_t* B1,
                                            int s, int g, int t) {
    const float* hb = g_hidden + s * 512;
#pragma unroll
    for (int c = 0; c < 4; c++) {
        int n = 8 * c + g;
        float2 lo = *(const float2*)(hb + n * REC + 2 * t);
        float2 hi = *(const float2*)(hb + n * REC + 2 * t + 8);
        B0[c] = pk2(lo.x, lo.y);
        B1[c] = pk2(hi.x, hi.y);
    }
}

// ---------------------------------------------------------------------------
// Kernel 3a: sum of exp(logit) via HMMA. grid(SLICES, SEQ), 256 threads.
// Warp w owns 25 consecutive tiles. Thread cols: b = 8c + 2t + {0,1}.
// ---------------------------------------------------------------------------
__global__ void __launch_bounds__(256) sumexp_mma_kernel() {
    const int slice = blockIdx.x;
    const int s     = blockIdx.y;
    const int tid   = threadIdx.x;
    const int wid   = tid >> 5, lane = tid & 31;
    const int g = lane >> 2, t = lane & 3;

    uint32_t B0[4], B1[4];
    make_bfrags(B0, B1, s, g, t);

    float acc[8];
#pragma unroll
    for (int k = 0; k < 8; k++) acc[k] = 0.0f;

    const int tile0 = slice * TILES_PER_CTA + wid * TILES_PER_W;
    const uint4* ap = &g_Vmma[(size_t)tile0 * 32 + lane];

    for (int i = 0; i < TILES_PER_W; i++) {
        uint4 a = ap[i * 32];
#pragma unroll
        for (int c = 0; c < 4; c++) {
            float d[4] = {0.f, 0.f, 0.f, 0.f};
            mma16816(d, a, B0[c], B1[c]);
            acc[2 * c]     += __expf(d[0]) + __expf(d[2]);
            acc[2 * c + 1] += __expf(d[1]) + __expf(d[3]);
        }
    }

    // reduce over g (lanes differing by 4, 8, 16); t determines cols
#pragma unroll
    for (int k = 0; k < 8; k++) {
        float v = acc[k];
        v += __shfl_xor_sync(0xffffffffu, v, 4);
        v += __shfl_xor_sync(0xffffffffu, v, 8);
        v += __shfl_xor_sync(0xffffffffu, v, 16);
        acc[k] = v;
    }

    __shared__ float red[WARPS][BATCH];
    if (lane < 4) {
#pragma unroll
        for (int c = 0; c < 4; c++) {
            red[wid][8 * c + 2 * lane]     = acc[2 * c];
            red[wid][8 * c + 2 * lane + 1] = acc[2 * c + 1];
        }
    }
    __syncthreads();
    if (tid < BATCH) {
        float tot = 0.f;
#pragma unroll
        for (int w = 0; w < WARPS; w++) tot += red[w][tid];
        atomicAdd(&g_sumexp[s * BATCH + tid], tot);
    }
}

// ---------------------------------------------------------------------------
// Kernel 3b: recompute logits via HMMA, write log_softmax.
// ---------------------------------------------------------------------------
__global__ void __launch_bounds__(256) write_mma_kernel(float* __restrict__ out) {
    const int slice = blockIdx.x;
    const int s     = blockIdx.y;
    const int tid   = threadIdx.x;
    const int wid   = tid >> 5, lane = tid & 31;
    const int g = lane >> 2, t = lane & 3;

    uint32_t B0[4], B1[4];
    make_bfrags(B0, B1, s, g, t);

    // -logZ for this thread's 8 batch columns
    float nz[8];
#pragma unroll
    for (int c = 0; c < 4; c++) {
        nz[2 * c]     = -__logf(g_sumexp[s * BATCH + 8 * c + 2 * t]);
        nz[2 * c + 1] = -__logf(g_sumexp[s * BATCH + 8 * c + 2 * t + 1]);
    }

    const int tile0 = slice * TILES_PER_CTA + wid * TILES_PER_W;
    const uint4* ap = &g_Vmma[(size_t)tile0 * 32 + lane];
    float* obase = out + (size_t)s * BATCH * VOCAB;

    for (int i = 0; i < TILES_PER_W; i++) {
        uint4 a = ap[i * 32];
        const int v = (tile0 + i) * 16 + g;
#pragma unroll
        for (int c = 0; c < 4; c++) {
            float d[4] = {0.f, 0.f, 0.f, 0.f};
            mma16816(d, a, B0[c], B1[c]);
            float* p0 = obase + (size_t)(8 * c + 2 * t)     * VOCAB + v;
            float* p1 = obase + (size_t)(8 * c + 2 * t + 1) * VOCAB + v;
            p0[0] = d[0] + nz[2 * c];
            p1[0] = d[1] + nz[2 * c + 1];
            p0[8] = d[2] + nz[2 * c];
            p1[8] = d[3] + nz[2 * c + 1];
        }
    }
}

// ---------------------------------------------------------------------------
extern "C" void kernel_launch(void* const* d_in, const int* in_sizes, int n_in,
                              void* d_out, int out_size) {
    const int*   tok = (const int*)  d_in[0];
    const float* emb = (const float*)d_in[1];
    const float* U   = (const float*)d_in[2];
    const float* W   = (const float*)d_in[3];
    const float* V   = (const float*)d_in[4];
    const float* b1  = (const float*)d_in[5];
    const float* b2  = (const float*)d_in[6];
    const float* h0  = (const float*)d_in[7];
    float* out = (float*)d_out;

    vprep_kernel<<<(NTILES * 32 + 255) / 256, 256>>>(V);
    iproj_kernel<<<(SEQ * BATCH * REC + 255) / 256, 256>>>(tok, emb, U, b1, b2);
    rnn_kernel<<<1, 256>>>(W, h0);
    dim3 grid(SLICES, SEQ);
    sumexp_mma_kernel<<<grid, 256>>>();
    write_mma_kernel<<<grid, 256>>>(out);
}